// round 1
// baseline (speedup 1.0000x reference)
#include <cuda_runtime.h>
#include <math.h>

// Problem constants
#define B_    8
#define C_    256
#define H_    64
#define W_    64
#define M_    (B_*H_*W_)   // 32768 positions
#define NH_   8
#define HD_   32

// Scratch (__device__ globals: allocation-free)
__device__ float g_y   [M_*C_];   // pooled, channels-last
__device__ float g_q   [M_*C_];
__device__ float g_k   [M_*C_];
__device__ float g_v   [M_*C_];
__device__ float g_ch  [M_*C_];
__device__ float g_t   [M_*128];  // gate hidden
__device__ float g_gate[M_*C_];
__device__ float g_att [M_*C_];   // attention out * (1+g)

__device__ __forceinline__ float* get_buf(int id) {
    switch (id) {
        case 0: return g_y;
        case 1: return g_q;
        case 2: return g_k;
        case 3: return g_v;
        case 4: return g_ch;
        case 5: return g_t;
        case 6: return g_gate;
        case 7: return g_att;
    }
    return nullptr;
}

// ---------------------------------------------------------------------------
// Kernel 1: 3x3 avg pool (stride 1, zero pad, /9) + transpose to [pos, C]
// grid (H, C/32, B), block 256. smem tile: 32 channels x 3 rows x 64 cols.
// ---------------------------------------------------------------------------
__global__ void __launch_bounds__(256) avgpool_kernel(const float* __restrict__ x)
{
    const int h  = blockIdx.x;
    const int c0 = blockIdx.y * 32;
    const int b  = blockIdx.z;
    __shared__ float s[96][65];   // [cc*3+dh][w], padded (stride 195 % 32 = 3)

    const int t = threadIdx.x;
    // load 96 rows (32 channels x 3 pool rows) of 64 pixels
    #pragma unroll 4
    for (int ri = 0; ri < 24; ri++) {
        int rowid = ri * 4 + (t >> 6);     // 0..95
        int w  = t & 63;
        int cc = rowid / 3;
        int dh = rowid - cc * 3;
        int hh = h + dh - 1;
        float v = 0.f;
        if (hh >= 0 && hh < H_)
            v = x[(((size_t)b * C_ + c0 + cc) * H_ + hh) * W_ + w];
        s[rowid][w] = v;
    }
    __syncthreads();

    const int cc = t & 31;
    const int wq = t >> 5;                 // 0..7
    #pragma unroll
    for (int wi = 0; wi < 8; wi++) {
        int w = wi * 8 + wq;
        float sum = 0.f;
        #pragma unroll
        for (int dh = 0; dh < 3; dh++) {
            const float* row = s[cc * 3 + dh];
            #pragma unroll
            for (int dw = -1; dw <= 1; dw++) {
                int w2 = w + dw;
                if (w2 >= 0 && w2 < W_) sum += row[w2];
            }
        }
        size_t pos = (size_t)b * 4096 + h * 64 + w;
        g_y[pos * C_ + c0 + cc] = sum * (1.f / 9.f);
    }
}

// ---------------------------------------------------------------------------
// Generic tiled fp32 GEMM:  C[M,N] = A[M,K] @ W[N,K]^T (+bias, +epilogue)
// BM=BN=128, BK=16, 256 threads, 8x8 microtile.
// EPI: 1 = relu -> C, 2 = sigmoid -> C, 3 = qkv split (permuted weight cols,
//      writes g_q/g_k/g_v/g_ch), 4 = bias + transposed NCHW store -> Cext
// AID selects the internal input buffer; CID the internal output (-1 = Cext).
// ---------------------------------------------------------------------------
template<int EPI, int AID, int CID>
__global__ void __launch_bounds__(256) gemm_kernel(
    const float* __restrict__ Wt, const float* __restrict__ bias,
    float* __restrict__ Cext, int N, int K)
{
    const int BM = 128, BN = 128, BK = 16;
    __shared__ float As[BK][BM];
    __shared__ float Bs[BK][BN];

    const float* __restrict__ A = get_buf(AID);
    float* __restrict__ C = (CID >= 0) ? get_buf(CID) : Cext;

    const int t  = threadIdx.x;
    const int tx = t & 15, ty = t >> 4;
    const int m0 = blockIdx.y * BM;
    const int n0 = blockIdx.x * BN;

    float acc[8][8];
    #pragma unroll
    for (int i = 0; i < 8; i++)
        #pragma unroll
        for (int j = 0; j < 8; j++) acc[i][j] = 0.f;

    const int lr = t >> 2;         // 0..63
    const int lk = (t & 3) * 4;    // 0,4,8,12

    for (int k0 = 0; k0 < K; k0 += BK) {
        #pragma unroll
        for (int i = 0; i < 2; i++) {
            int row = lr + i * 64;
            float4 av = *(const float4*)&A[(size_t)(m0 + row) * K + k0 + lk];
            As[lk + 0][row] = av.x; As[lk + 1][row] = av.y;
            As[lk + 2][row] = av.z; As[lk + 3][row] = av.w;
        }
        #pragma unroll
        for (int i = 0; i < 2; i++) {
            int row = lr + i * 64;         // n within tile
            int n = n0 + row;
            int wr = (EPI == 3) ? ((n & 255) * 4 + (n >> 8)) : n;
            float4 bv = *(const float4*)&Wt[(size_t)wr * K + k0 + lk];
            Bs[lk + 0][row] = bv.x; Bs[lk + 1][row] = bv.y;
            Bs[lk + 2][row] = bv.z; Bs[lk + 3][row] = bv.w;
        }
        __syncthreads();
        #pragma unroll
        for (int kk = 0; kk < BK; kk++) {
            float ar[8], br[8];
            *(float4*)&ar[0] = *(const float4*)&As[kk][ty * 8];
            *(float4*)&ar[4] = *(const float4*)&As[kk][ty * 8 + 4];
            *(float4*)&br[0] = *(const float4*)&Bs[kk][tx * 8];
            *(float4*)&br[4] = *(const float4*)&Bs[kk][tx * 8 + 4];
            #pragma unroll
            for (int im = 0; im < 8; im++)
                #pragma unroll
                for (int in = 0; in < 8; in++)
                    acc[im][in] += ar[im] * br[in];
        }
        __syncthreads();
    }

    #pragma unroll
    for (int im = 0; im < 8; im++) {
        int m = m0 + ty * 8 + im;
        #pragma unroll
        for (int in = 0; in < 8; in++) {
            int n = n0 + tx * 8 + in;
            float v = acc[im][in];
            if (EPI == 3) {
                int orig = (n & 255) * 4 + (n >> 8);   // source column of W_qkv
                v += bias[orig];
                float* dst = (n < 256) ? g_q : (n < 512) ? g_k
                           : (n < 768) ? g_v : g_ch;
                dst[(size_t)m * 256 + (n & 255)] = v;
            } else {
                v += bias[n];
                if (EPI == 1) v = fmaxf(v, 0.f);
                if (EPI == 2) v = 1.f / (1.f + expf(-v));
                if (EPI == 4) {
                    int b  = m >> 12;
                    int hw = m & 4095;
                    C[((size_t)(b * 256 + n)) * 4096 + hw] = v;  // [B,C,H,W]
                } else {
                    C[(size_t)m * N + n] = v;
                }
            }
        }
    }
}

// ---------------------------------------------------------------------------
// Kernel: 3x3 local-window attention + gate multiply.
// One block per position (256 thr), one warp per head, lane = head-dim chan.
// OOB neighbors: logit = 0 (reference zero-pads k), value = 0. Softmax over 9.
// ---------------------------------------------------------------------------
__global__ void __launch_bounds__(256) attn_kernel()
{
    const int pos  = blockIdx.x;
    const int head = threadIdx.x >> 5;
    const int lane = threadIdx.x & 31;
    const int hw = pos & 4095;
    const int iy = hw >> 6, ix = hw & 63;
    const int ch = head * HD_ + lane;
    const size_t base = (size_t)pos * C_ + ch;

    const float q = g_q[base];
    float logit[9], vv[9];
    #pragma unroll
    for (int j = 0; j < 9; j++) {
        int dy = j / 3 - 1, dx = j % 3 - 1;
        int ny = iy + dy, nx = ix + dx;
        float p = 0.f, val = 0.f;
        if (ny >= 0 && ny < H_ && nx >= 0 && nx < W_) {
            int npos = pos + dy * 64 + dx;   // same batch image
            size_t nb = (size_t)npos * C_ + ch;
            p   = q * g_k[nb];
            val = g_v[nb];
        }
        #pragma unroll
        for (int off = 16; off; off >>= 1)
            p += __shfl_xor_sync(0xffffffffu, p, off);
        logit[j] = p * 0.17677669529663687f;   // 32^-0.5 (OOB -> exactly 0)
        vv[j] = val;
    }

    float mx = logit[0];
    #pragma unroll
    for (int j = 1; j < 9; j++) mx = fmaxf(mx, logit[j]);
    float e[9], s = 0.f;
    #pragma unroll
    for (int j = 0; j < 9; j++) { e[j] = __expf(logit[j] - mx); s += e[j]; }
    const float inv = 1.f / s;
    float o = 0.f;
    #pragma unroll
    for (int j = 0; j < 9; j++) o += e[j] * inv * vv[j];

    const float gg = g_gate[base];
    g_att[base] = o * (1.f + gg);
}

// ---------------------------------------------------------------------------
extern "C" void kernel_launch(void* const* d_in, const int* in_sizes, int n_in,
                              void* d_out, int out_size)
{
    const float* x     = (const float*)d_in[0];
    const float* W_qkv = (const float*)d_in[1];
    const float* b_qkv = (const float*)d_in[2];
    const float* W1    = (const float*)d_in[3];
    const float* b1    = (const float*)d_in[4];
    const float* W2    = (const float*)d_in[5];
    const float* b2    = (const float*)d_in[6];
    const float* Wp    = (const float*)d_in[7];
    const float* bp    = (const float*)d_in[8];
    float* out = (float*)d_out;

    // 1) avg pool + transpose -> g_y
    avgpool_kernel<<<dim3(H_, C_ / 32, B_), 256>>>(x);

    // 2) QKV GEMM (N=1024, K=256), permuted split epilogue -> g_q/g_k/g_v/g_ch
    gemm_kernel<3, 0, 1><<<dim3(1024 / 128, M_ / 128), 256>>>(
        W_qkv, b_qkv, nullptr, 1024, 256);

    // 3) gate hidden: relu(ch @ W1^T + b1) -> g_t  (N=128, K=256)
    gemm_kernel<1, 4, 5><<<dim3(1, M_ / 128), 256>>>(W1, b1, nullptr, 128, 256);

    // 4) gate: sigmoid(t @ W2^T + b2) -> g_gate  (N=256, K=128)
    gemm_kernel<2, 5, 6><<<dim3(2, M_ / 128), 256>>>(W2, b2, nullptr, 256, 128);

    // 5) local attention + (1+g) -> g_att
    attn_kernel<<<M_, 256>>>();

    // 6) projection (N=256, K=256) + bias + transposed NCHW store -> d_out
    gemm_kernel<4, 7, -1><<<dim3(2, M_ / 128), 256>>>(Wp, bp, out, 256, 256);
}

// round 5
// speedup vs baseline: 2.1880x; 2.1880x over previous
#include <cuda_runtime.h>
#include <cuda_bf16.h>
#include <math.h>
#include <stdint.h>

#define B_    8
#define C_    256
#define H_    64
#define W_    64
#define M_    32768
#define NH_   8
#define HD_   32

// ---------------------------------------------------------------------------
// Scratch buffers (__device__ globals: allocation-free)
// ---------------------------------------------------------------------------
__device__ float g_q   [M_*C_];
__device__ float g_k   [M_*C_];
__device__ float g_v   [M_*C_];
__device__ float g_gate[M_*C_];

__device__ __nv_bfloat16 g_yh [M_*C_],  g_yl [M_*C_];
__device__ __nv_bfloat16 g_chh[M_*C_],  g_chl[M_*C_];
__device__ __nv_bfloat16 g_th [M_*128], g_tl [M_*128];
__device__ __nv_bfloat16 g_ath[M_*C_],  g_atl[M_*C_];
__device__ __nv_bfloat16 g_wqh[1024*256], g_wql[1024*256];
__device__ __nv_bfloat16 g_w1h[128*256],  g_w1l[128*256];
__device__ __nv_bfloat16 g_w2h[256*128],  g_w2l[256*128];
__device__ __nv_bfloat16 g_wph[256*256],  g_wpl[256*256];

__device__ __forceinline__ const __nv_bfloat16* bf_buf(int id) {
    switch (id) {
        case 0:  return g_yh;  case 1:  return g_yl;
        case 2:  return g_chh; case 3:  return g_chl;
        case 4:  return g_th;  case 5:  return g_tl;
        case 6:  return g_ath; case 7:  return g_atl;
        case 8:  return g_wqh; case 9:  return g_wql;
        case 10: return g_w1h; case 11: return g_w1l;
        case 12: return g_w2h; case 13: return g_w2l;
        case 14: return g_wph; case 15: return g_wpl;
    }
    return nullptr;
}

__device__ __forceinline__ void split_bf16(float v, __nv_bfloat16& h, __nv_bfloat16& l) {
    h = __float2bfloat16(v);
    l = __float2bfloat16(v - __bfloat162float(h));
}

// ---------------------------------------------------------------------------
// sm_80-compatible async-copy / ldmatrix / mma.sync helpers
// ---------------------------------------------------------------------------
__device__ __forceinline__ uint32_t smem_to_u32(const void* p) {
    uint32_t a;
    asm("{ .reg .u64 t; cvta.to.shared.u64 t, %1; cvt.u32.u64 %0, t; }"
        : "=r"(a) : "l"(p));
    return a;
}
__device__ __forceinline__ void cp_async16(uint32_t sa, const void* g) {
    asm volatile("cp.async.cg.shared.global [%0], [%1], 16;" :: "r"(sa), "l"(g));
}
#define CP_COMMIT() asm volatile("cp.async.commit_group;" ::: "memory")
#define CP_WAIT(n)  asm volatile("cp.async.wait_group %0;" :: "n"(n) : "memory")

__device__ __forceinline__ void ldsm4(uint32_t* r, uint32_t a) {
    asm volatile("ldmatrix.sync.aligned.m8n8.x4.shared.b16 {%0,%1,%2,%3}, [%4];"
        : "=r"(r[0]), "=r"(r[1]), "=r"(r[2]), "=r"(r[3]) : "r"(a));
}
__device__ __forceinline__ void mma16816(float* c, const uint32_t* a,
                                         uint32_t b0, uint32_t b1) {
    asm volatile(
        "mma.sync.aligned.m16n8k16.row.col.f32.bf16.bf16.f32 "
        "{%0,%1,%2,%3}, {%4,%5,%6,%7}, {%8,%9}, {%0,%1,%2,%3};"
        : "+f"(c[0]), "+f"(c[1]), "+f"(c[2]), "+f"(c[3])
        : "r"(a[0]), "r"(a[1]), "r"(a[2]), "r"(a[3]), "r"(b0), "r"(b1));
}

// ---------------------------------------------------------------------------
// Kernel 1: 3x3 avg pool + transpose to [pos, C], output split into bf16 hi/lo
// ---------------------------------------------------------------------------
__global__ void __launch_bounds__(256) avgpool_kernel(const float* __restrict__ x)
{
    const int h  = blockIdx.x;
    const int c0 = blockIdx.y * 32;
    const int b  = blockIdx.z;
    __shared__ float s[96][65];

    const int t = threadIdx.x;
    #pragma unroll 4
    for (int ri = 0; ri < 24; ri++) {
        int rowid = ri * 4 + (t >> 6);
        int w  = t & 63;
        int cc = rowid / 3;
        int dh = rowid - cc * 3;
        int hh = h + dh - 1;
        float v = 0.f;
        if (hh >= 0 && hh < H_)
            v = x[(((size_t)b * C_ + c0 + cc) * H_ + hh) * W_ + w];
        s[rowid][w] = v;
    }
    __syncthreads();

    const int cc = t & 31;
    const int wq = t >> 5;
    #pragma unroll
    for (int wi = 0; wi < 8; wi++) {
        int w = wi * 8 + wq;
        float sum = 0.f;
        #pragma unroll
        for (int dh = 0; dh < 3; dh++) {
            const float* row = s[cc * 3 + dh];
            #pragma unroll
            for (int dw = -1; dw <= 1; dw++) {
                int w2 = w + dw;
                if (w2 >= 0 && w2 < W_) sum += row[w2];
            }
        }
        size_t pos = (size_t)b * 4096 + h * 64 + w;
        __nv_bfloat16 hi, lo;
        split_bf16(sum * (1.f / 9.f), hi, lo);
        g_yh[pos * C_ + c0 + cc] = hi;
        g_yl[pos * C_ + c0 + cc] = lo;
    }
}

// ---------------------------------------------------------------------------
// Kernel: weight conversion to bf16 hi/lo (+ QKV column permutation)
// ---------------------------------------------------------------------------
__global__ void __launch_bounds__(256) convert_weights(
    const float* __restrict__ Wq, const float* __restrict__ W1,
    const float* __restrict__ W2, const float* __restrict__ Wp)
{
    int i = blockIdx.x * 256 + threadIdx.x;
    if (i < 262144) {
        int n = i >> 8, kk = i & 255;
        int orig = (n & 255) * 4 + (n >> 8);
        split_bf16(Wq[orig * 256 + kk], g_wqh[i], g_wql[i]);
    } else if (i < 294912) {
        int j = i - 262144;
        split_bf16(W1[j], g_w1h[j], g_w1l[j]);
    } else if (i < 327680) {
        int j = i - 294912;
        split_bf16(W2[j], g_w2h[j], g_w2l[j]);
    } else if (i < 393216) {
        int j = i - 327680;
        split_bf16(Wp[j], g_wph[j], g_wpl[j]);
    }
}

// ---------------------------------------------------------------------------
// mma.sync bf16 GEMM with 3-product precision splitting.
// C[M,N] = A[M,K] @ W[N,K]^T, fp32 accum.  BM=BN=128, BK=32, 256 threads.
// Warp tile 32x64 (wm = w&3 selects 32 rows, wn = w>>2 selects 64 cols).
// Smem per stage: Ah|Al|Bh|Bl, each 128 rows x 32 bf16 padded to 40 (80B).
// B (W[n][k] row-major == K-major col operand) loads with NON-trans ldmatrix.
// EPI: 0 QKV split   1 relu->bf16   2 sigmoid->gate   3 bias+NCHW store
// ---------------------------------------------------------------------------
#define TILE_B   10240          // 128 * 80
#define STAGE_B  (4 * TILE_B)   // 40960
#define SMEM_SZ  (2 * STAGE_B)  // 81920

template<int EPI, int AID, int BID, int KMAT>
__global__ void __launch_bounds__(256, 1) mma_gemm(
    const float* __restrict__ bias, float* __restrict__ outp)
{
    extern __shared__ char sm[];
    const uint32_t smb = smem_to_u32(sm);
    const int t = threadIdx.x;
    const int wid = t >> 5, lane = t & 31;
    const int wm = wid & 3, wn = wid >> 2;
    const int m0 = blockIdx.y * 128;
    const int n0 = blockIdx.x * 128;
    constexpr int S = KMAT / 32;

    const __nv_bfloat16* src[4] = { bf_buf(AID), bf_buf(AID + 1),
                                    bf_buf(BID), bf_buf(BID + 1) };

    float acc[2][8][4];
    #pragma unroll
    for (int i = 0; i < 2; i++)
        #pragma unroll
        for (int j = 0; j < 8; j++)
            #pragma unroll
            for (int q = 0; q < 4; q++) acc[i][j][q] = 0.f;

    // ldmatrix lane addressing (same pattern for A and B, both non-trans):
    // lanes 0-7:(r0-7,k0) 8-15:(r0-7,k8) 16-23:(r8-15,k0) 24-31:(r8-15,k8)
    const int ar = lane & 15;
    const int ac = (lane >> 4) << 3;
    const int br = (lane & 7) + ((lane >> 4) << 3);
    const int bc = ((lane >> 3) & 1) << 3;

    auto load_stage = [&](int s) {
        const uint32_t sb = smb + (uint32_t)(s & 1) * STAGE_B;
        const int k0 = s * 32;
        #pragma unroll
        for (int tile = 0; tile < 4; tile++) {
            const __nv_bfloat16* sp = src[tile];
            const int rb = (tile < 2) ? m0 : n0;
            #pragma unroll
            for (int i = 0; i < 2; i++) {
                int chunk = i * 256 + t;
                int row = chunk >> 2, cc = chunk & 3;
                cp_async16(sb + tile * TILE_B + row * 80 + cc * 16,
                           sp + (size_t)(rb + row) * KMAT + k0 + cc * 8);
            }
        }
        CP_COMMIT();
    };

    load_stage(0);
    for (int s = 0; s < S; s++) {
        if (s + 1 < S) { load_stage(s + 1); CP_WAIT(1); }
        else           { CP_WAIT(0); }
        __syncthreads();

        const uint32_t base = smb + (uint32_t)(s & 1) * STAGE_B;
        #pragma unroll
        for (int ks = 0; ks < 2; ks++) {
            uint32_t ah[2][4], al[2][4];
            #pragma unroll
            for (int mt = 0; mt < 2; mt++) {
                uint32_t off = (uint32_t)((wm * 32 + mt * 16 + ar) * 80
                                          + (ks * 16 + ac) * 2);
                ldsm4(ah[mt], base + off);
                ldsm4(al[mt], base + TILE_B + off);
            }
            uint32_t bh[16], bl[16];
            #pragma unroll
            for (int p = 0; p < 4; p++) {
                uint32_t off = (uint32_t)((wn * 64 + p * 16 + br) * 80
                                          + (ks * 16 + bc) * 2);
                ldsm4(&bh[p * 4], base + 2 * TILE_B + off);
                ldsm4(&bl[p * 4], base + 3 * TILE_B + off);
            }
            #pragma unroll
            for (int mt = 0; mt < 2; mt++)
                #pragma unroll
                for (int nt = 0; nt < 8; nt++) {
                    const int bi = (nt >> 1) * 4 + (nt & 1) * 2;
                    mma16816(acc[mt][nt], ah[mt], bh[bi], bh[bi + 1]);
                    mma16816(acc[mt][nt], ah[mt], bl[bi], bl[bi + 1]);
                    mma16816(acc[mt][nt], al[mt], bh[bi], bh[bi + 1]);
                }
        }
        __syncthreads();
    }

    // ------------------------- epilogue -------------------------
    // acc[mt][nt]: c0,c1 at (m, n),(m, n+1); c2,c3 at (m+8, n),(m+8, n+1)
    // m = m0 + wm*32 + mt*16 + lane/4 ; n = n0 + wn*64 + nt*8 + 2*(lane&3)
    const int mrow = m0 + wm * 32 + (lane >> 2);
    const int ncol = wn * 64 + (lane & 3) * 2;

    if (EPI == 0) {
        const int g = n0 >> 8;
        #pragma unroll
        for (int mt = 0; mt < 2; mt++) {
            #pragma unroll
            for (int nt = 0; nt < 8; nt++) {
                const int m  = mrow + mt * 16;
                const int ch = ((n0 + ncol) & 255) + nt * 8;
                float v0 = acc[mt][nt][0] + bias[(ch + 0) * 4 + g];
                float v1 = acc[mt][nt][1] + bias[(ch + 1) * 4 + g];
                float v2 = acc[mt][nt][2] + bias[(ch + 0) * 4 + g];
                float v3 = acc[mt][nt][3] + bias[(ch + 1) * 4 + g];
                if (g < 3) {
                    float* dst = (g == 0) ? g_q : (g == 1) ? g_k : g_v;
                    *(float2*)&dst[(size_t)m * 256 + ch]       = make_float2(v0, v1);
                    *(float2*)&dst[(size_t)(m + 8) * 256 + ch] = make_float2(v2, v3);
                } else {
                    __nv_bfloat16 h0, l0, h1, l1;
                    split_bf16(v0, h0, l0); split_bf16(v1, h1, l1);
                    *(__nv_bfloat162*)&g_chh[(size_t)m * 256 + ch] = __nv_bfloat162(h0, h1);
                    *(__nv_bfloat162*)&g_chl[(size_t)m * 256 + ch] = __nv_bfloat162(l0, l1);
                    split_bf16(v2, h0, l0); split_bf16(v3, h1, l1);
                    *(__nv_bfloat162*)&g_chh[(size_t)(m + 8) * 256 + ch] = __nv_bfloat162(h0, h1);
                    *(__nv_bfloat162*)&g_chl[(size_t)(m + 8) * 256 + ch] = __nv_bfloat162(l0, l1);
                }
            }
        }
    } else if (EPI == 1) {
        #pragma unroll
        for (int mt = 0; mt < 2; mt++)
            #pragma unroll
            for (int nt = 0; nt < 8; nt++) {
                const int m = mrow + mt * 16;
                const int n = ncol + nt * 8;          // N = 128, n0 = 0
                float v0 = fmaxf(acc[mt][nt][0] + bias[n],     0.f);
                float v1 = fmaxf(acc[mt][nt][1] + bias[n + 1], 0.f);
                float v2 = fmaxf(acc[mt][nt][2] + bias[n],     0.f);
                float v3 = fmaxf(acc[mt][nt][3] + bias[n + 1], 0.f);
                __nv_bfloat16 h0, l0, h1, l1;
                split_bf16(v0, h0, l0); split_bf16(v1, h1, l1);
                *(__nv_bfloat162*)&g_th[(size_t)m * 128 + n] = __nv_bfloat162(h0, h1);
                *(__nv_bfloat162*)&g_tl[(size_t)m * 128 + n] = __nv_bfloat162(l0, l1);
                split_bf16(v2, h0, l0); split_bf16(v3, h1, l1);
                *(__nv_bfloat162*)&g_th[(size_t)(m + 8) * 128 + n] = __nv_bfloat162(h0, h1);
                *(__nv_bfloat162*)&g_tl[(size_t)(m + 8) * 128 + n] = __nv_bfloat162(l0, l1);
            }
    } else if (EPI == 2) {
        #pragma unroll
        for (int mt = 0; mt < 2; mt++)
            #pragma unroll
            for (int nt = 0; nt < 8; nt++) {
                const int m = mrow + mt * 16;
                const int n = n0 + ncol + nt * 8;
                float v0 = 1.f / (1.f + expf(-(acc[mt][nt][0] + bias[n])));
                float v1 = 1.f / (1.f + expf(-(acc[mt][nt][1] + bias[n + 1])));
                float v2 = 1.f / (1.f + expf(-(acc[mt][nt][2] + bias[n])));
                float v3 = 1.f / (1.f + expf(-(acc[mt][nt][3] + bias[n + 1])));
                *(float2*)&g_gate[(size_t)m * 256 + n]       = make_float2(v0, v1);
                *(float2*)&g_gate[(size_t)(m + 8) * 256 + n] = make_float2(v2, v3);
            }
    } else { // EPI == 3: bias + smem transpose + coalesced NCHW store
        float* smT = (float*)sm;                  // [128 n][stride 132 m]
        const int ml = mrow - m0;
        #pragma unroll
        for (int mt = 0; mt < 2; mt++)
            #pragma unroll
            for (int nt = 0; nt < 8; nt++) {
                const int n = ncol + nt * 8;      // local n (0..127)
                smT[(n)     * 132 + ml + mt * 16]     = acc[mt][nt][0] + bias[n0 + n];
                smT[(n + 1) * 132 + ml + mt * 16]     = acc[mt][nt][1] + bias[n0 + n + 1];
                smT[(n)     * 132 + ml + mt * 16 + 8] = acc[mt][nt][2] + bias[n0 + n];
                smT[(n + 1) * 132 + ml + mt * 16 + 8] = acc[mt][nt][3] + bias[n0 + n + 1];
            }
        __syncthreads();
        const int nl = t >> 1, half = t & 1;
        const int bi = m0 >> 12, hw0 = m0 & 4095;
        float* orow = outp + ((size_t)(bi * 256 + n0 + nl)) * 4096 + hw0 + half * 64;
        #pragma unroll
        for (int i = 0; i < 16; i++)
            *(float4*)&orow[i * 4] = *(float4*)&smT[nl * 132 + half * 64 + i * 4];
    }
}

// ---------------------------------------------------------------------------
// Kernel: 3x3 local-window attention + gate; writes bf16 hi/lo for proj GEMM
// ---------------------------------------------------------------------------
__global__ void __launch_bounds__(256) attn_kernel()
{
    const int pos  = blockIdx.x;
    const int head = threadIdx.x >> 5;
    const int lane = threadIdx.x & 31;
    const int hw = pos & 4095;
    const int iy = hw >> 6, ix = hw & 63;
    const int ch = head * HD_ + lane;
    const size_t base = (size_t)pos * C_ + ch;

    const float q = g_q[base];
    float logit[9], vv[9];
    #pragma unroll
    for (int j = 0; j < 9; j++) {
        int dy = j / 3 - 1, dx = j % 3 - 1;
        int ny = iy + dy, nx = ix + dx;
        float p = 0.f, val = 0.f;
        if (ny >= 0 && ny < H_ && nx >= 0 && nx < W_) {
            int npos = pos + dy * 64 + dx;
            size_t nb = (size_t)npos * C_ + ch;
            p   = q * g_k[nb];
            val = g_v[nb];
        }
        #pragma unroll
        for (int off = 16; off; off >>= 1)
            p += __shfl_xor_sync(0xffffffffu, p, off);
        logit[j] = p * 0.17677669529663687f;
        vv[j] = val;
    }

    float mx = logit[0];
    #pragma unroll
    for (int j = 1; j < 9; j++) mx = fmaxf(mx, logit[j]);
    float e[9], ssum = 0.f;
    #pragma unroll
    for (int j = 0; j < 9; j++) { e[j] = __expf(logit[j] - mx); ssum += e[j]; }
    const float inv = 1.f / ssum;
    float o = 0.f;
    #pragma unroll
    for (int j = 0; j < 9; j++) o += e[j] * inv * vv[j];

    const float r = o * (1.f + g_gate[base]);
    __nv_bfloat16 hi, lo;
    split_bf16(r, hi, lo);
    g_ath[base] = hi;
    g_atl[base] = lo;
}

// ---------------------------------------------------------------------------
extern "C" void kernel_launch(void* const* d_in, const int* in_sizes, int n_in,
                              void* d_out, int out_size)
{
    const float* x     = (const float*)d_in[0];
    const float* W_qkv = (const float*)d_in[1];
    const float* b_qkv = (const float*)d_in[2];
    const float* W1    = (const float*)d_in[3];
    const float* b1    = (const float*)d_in[4];
    const float* W2    = (const float*)d_in[5];
    const float* b2    = (const float*)d_in[6];
    const float* Wp    = (const float*)d_in[7];
    const float* bp    = (const float*)d_in[8];
    float* out = (float*)d_out;

    cudaFuncSetAttribute(mma_gemm<0, 0,  8, 256>, cudaFuncAttributeMaxDynamicSharedMemorySize, SMEM_SZ);
    cudaFuncSetAttribute(mma_gemm<1, 2, 10, 256>, cudaFuncAttributeMaxDynamicSharedMemorySize, SMEM_SZ);
    cudaFuncSetAttribute(mma_gemm<2, 4, 12, 128>, cudaFuncAttributeMaxDynamicSharedMemorySize, SMEM_SZ);
    cudaFuncSetAttribute(mma_gemm<3, 6, 14, 256>, cudaFuncAttributeMaxDynamicSharedMemorySize, SMEM_SZ);

    // 1) weight conversion (bf16 hi/lo, QKV permuted) + avg pool
    convert_weights<<<1536, 256>>>(W_qkv, W1, W2, Wp);
    avgpool_kernel<<<dim3(H_, C_ / 32, B_), 256>>>(x);

    // 2) QKV GEMM: [32768,1024] = y @ Wqkv^T  -> q/k/v fp32, ch bf16
    mma_gemm<0, 0, 8, 256><<<dim3(8, 256), 256, SMEM_SZ>>>(b_qkv, nullptr);

    // 3) gate hidden: relu(ch @ W1^T + b1) -> th/tl  (N=128)
    mma_gemm<1, 2, 10, 256><<<dim3(1, 256), 256, SMEM_SZ>>>(b1, nullptr);

    // 4) gate: sigmoid(t @ W2^T + b2) -> g_gate  (N=256, K=128)
    mma_gemm<2, 4, 12, 128><<<dim3(2, 256), 256, SMEM_SZ>>>(b2, nullptr);

    // 5) local attention + (1+g) -> ath/atl bf16
    attn_kernel<<<M_, 256>>>();

    // 6) projection + bias + NCHW store -> d_out
    mma_gemm<3, 6, 14, 256><<<dim3(2, 256), 256, SMEM_SZ>>>(bp, out);
}

// round 6
// speedup vs baseline: 2.5491x; 1.1650x over previous
#include <cuda_runtime.h>
#include <cuda_bf16.h>
#include <math.h>
#include <stdint.h>

#define B_    8
#define C_    256
#define H_    64
#define W_    64
#define M_    32768
#define NH_   8
#define HD_   32

// ---------------------------------------------------------------------------
// Scratch buffers (__device__ globals: allocation-free)
// ---------------------------------------------------------------------------
__device__ float g_q   [M_*C_];
__device__ float g_k   [M_*C_];
__device__ float g_v   [M_*C_];
__device__ float g_gate[M_*C_];

__device__ __nv_bfloat16 g_yh [M_*C_],  g_yl [M_*C_];
__device__ __nv_bfloat16 g_chh[M_*C_],  g_chl[M_*C_];
__device__ __nv_bfloat16 g_th [M_*128], g_tl [M_*128];
__device__ __nv_bfloat16 g_ath[M_*C_],  g_atl[M_*C_];
__device__ __nv_bfloat16 g_wqh[1024*256], g_wql[1024*256];
__device__ __nv_bfloat16 g_w1h[128*256],  g_w1l[128*256];
__device__ __nv_bfloat16 g_w2h[256*128],  g_w2l[256*128];
__device__ __nv_bfloat16 g_wph[256*256],  g_wpl[256*256];

__device__ __forceinline__ const __nv_bfloat16* bf_buf(int id) {
    switch (id) {
        case 0:  return g_yh;  case 1:  return g_yl;
        case 2:  return g_chh; case 3:  return g_chl;
        case 4:  return g_th;  case 5:  return g_tl;
        case 6:  return g_ath; case 7:  return g_atl;
        case 8:  return g_wqh; case 9:  return g_wql;
        case 10: return g_w1h; case 11: return g_w1l;
        case 12: return g_w2h; case 13: return g_w2l;
        case 14: return g_wph; case 15: return g_wpl;
    }
    return nullptr;
}

__device__ __forceinline__ void split_bf16(float v, __nv_bfloat16& h, __nv_bfloat16& l) {
    h = __float2bfloat16(v);
    l = __float2bfloat16(v - __bfloat162float(h));
}

// ---------------------------------------------------------------------------
// sm_80-compatible async-copy / ldmatrix / mma.sync helpers
// ---------------------------------------------------------------------------
__device__ __forceinline__ uint32_t smem_to_u32(const void* p) {
    uint32_t a;
    asm("{ .reg .u64 t; cvta.to.shared.u64 t, %1; cvt.u32.u64 %0, t; }"
        : "=r"(a) : "l"(p));
    return a;
}
__device__ __forceinline__ void cp_async16(uint32_t sa, const void* g) {
    asm volatile("cp.async.cg.shared.global [%0], [%1], 16;" :: "r"(sa), "l"(g));
}
#define CP_COMMIT() asm volatile("cp.async.commit_group;" ::: "memory")
#define CP_WAIT(n)  asm volatile("cp.async.wait_group %0;" :: "n"(n) : "memory")

__device__ __forceinline__ void ldsm4(uint32_t* r, uint32_t a) {
    asm volatile("ldmatrix.sync.aligned.m8n8.x4.shared.b16 {%0,%1,%2,%3}, [%4];"
        : "=r"(r[0]), "=r"(r[1]), "=r"(r[2]), "=r"(r[3]) : "r"(a));
}
__device__ __forceinline__ void mma16816(float* c, const uint32_t* a,
                                         uint32_t b0, uint32_t b1) {
    asm volatile(
        "mma.sync.aligned.m16n8k16.row.col.f32.bf16.bf16.f32 "
        "{%0,%1,%2,%3}, {%4,%5,%6,%7}, {%8,%9}, {%0,%1,%2,%3};"
        : "+f"(c[0]), "+f"(c[1]), "+f"(c[2]), "+f"(c[3])
        : "r"(a[0]), "r"(a[1]), "r"(a[2]), "r"(a[3]), "r"(b0), "r"(b1));
}

// ---------------------------------------------------------------------------
// Kernel 1: 3x3 avg pool + transpose to [pos, C], output split into bf16 hi/lo
// ---------------------------------------------------------------------------
__global__ void __launch_bounds__(256) avgpool_kernel(const float* __restrict__ x)
{
    const int h  = blockIdx.x;
    const int c0 = blockIdx.y * 32;
    const int b  = blockIdx.z;
    __shared__ float s[96][65];

    const int t = threadIdx.x;
    #pragma unroll 4
    for (int ri = 0; ri < 24; ri++) {
        int rowid = ri * 4 + (t >> 6);
        int w  = t & 63;
        int cc = rowid / 3;
        int dh = rowid - cc * 3;
        int hh = h + dh - 1;
        float v = 0.f;
        if (hh >= 0 && hh < H_)
            v = x[(((size_t)b * C_ + c0 + cc) * H_ + hh) * W_ + w];
        s[rowid][w] = v;
    }
    __syncthreads();

    const int cc = t & 31;
    const int wq = t >> 5;
    #pragma unroll
    for (int wi = 0; wi < 8; wi++) {
        int w = wi * 8 + wq;
        float sum = 0.f;
        #pragma unroll
        for (int dh = 0; dh < 3; dh++) {
            const float* row = s[cc * 3 + dh];
            #pragma unroll
            for (int dw = -1; dw <= 1; dw++) {
                int w2 = w + dw;
                if (w2 >= 0 && w2 < W_) sum += row[w2];
            }
        }
        size_t pos = (size_t)b * 4096 + h * 64 + w;
        __nv_bfloat16 hi, lo;
        split_bf16(sum * (1.f / 9.f), hi, lo);
        g_yh[pos * C_ + c0 + cc] = hi;
        g_yl[pos * C_ + c0 + cc] = lo;
    }
}

// ---------------------------------------------------------------------------
// Kernel: weight conversion to bf16 hi/lo (+ QKV column permutation)
// ---------------------------------------------------------------------------
__global__ void __launch_bounds__(256) convert_weights(
    const float* __restrict__ Wq, const float* __restrict__ W1,
    const float* __restrict__ W2, const float* __restrict__ Wp)
{
    int i = blockIdx.x * 256 + threadIdx.x;
    if (i < 262144) {
        int n = i >> 8, kk = i & 255;
        int orig = (n & 255) * 4 + (n >> 8);
        split_bf16(Wq[orig * 256 + kk], g_wqh[i], g_wql[i]);
    } else if (i < 294912) {
        int j = i - 262144;
        split_bf16(W1[j], g_w1h[j], g_w1l[j]);
    } else if (i < 327680) {
        int j = i - 294912;
        split_bf16(W2[j], g_w2h[j], g_w2l[j]);
    } else if (i < 393216) {
        int j = i - 327680;
        split_bf16(Wp[j], g_wph[j], g_wpl[j]);
    }
}

// ---------------------------------------------------------------------------
// mma.sync bf16 GEMM with 3-product precision splitting.
// C[M,N] = A[M,K] @ W[N,K]^T, fp32 accum.  BM=BN=128, BK=32, 256 threads.
// __launch_bounds__(256, 2): cap regs at 128 so 2 CTAs co-reside per SM
// (16 warps/SM) — Round-5 profile showed occ=12.5%, issue=13%: latency-bound.
// Warp tile 32x64. Smem/stage: Ah|Al|Bh|Bl, 128 rows x 32 bf16 pad 40 (80B).
// EPI: 0 QKV split   1 relu->bf16   2 sigmoid->gate   3 bias+NCHW store
// ---------------------------------------------------------------------------
#define TILE_B   10240          // 128 * 80
#define STAGE_B  (4 * TILE_B)   // 40960
#define SMEM_SZ  (2 * STAGE_B)  // 81920

template<int EPI, int AID, int BID, int KMAT>
__global__ void __launch_bounds__(256, 2) mma_gemm(
    const float* __restrict__ bias, float* __restrict__ outp)
{
    extern __shared__ char sm[];
    const uint32_t smb = smem_to_u32(sm);
    const int t = threadIdx.x;
    const int wid = t >> 5, lane = t & 31;
    const int wm = wid & 3, wn = wid >> 2;
    const int m0 = blockIdx.y * 128;
    const int n0 = blockIdx.x * 128;
    constexpr int S = KMAT / 32;

    const __nv_bfloat16* src[4] = { bf_buf(AID), bf_buf(AID + 1),
                                    bf_buf(BID), bf_buf(BID + 1) };

    float acc[2][8][4];
    #pragma unroll
    for (int i = 0; i < 2; i++)
        #pragma unroll
        for (int j = 0; j < 8; j++)
            #pragma unroll
            for (int q = 0; q < 4; q++) acc[i][j][q] = 0.f;

    // ldmatrix lane addressing (same pattern for A and B, both non-trans):
    // lanes 0-7:(r0-7,k0) 8-15:(r0-7,k8) 16-23:(r8-15,k0) 24-31:(r8-15,k8)
    const int ar = lane & 15;
    const int ac = (lane >> 4) << 3;
    const int br = (lane & 7) + ((lane >> 4) << 3);
    const int bc = ((lane >> 3) & 1) << 3;

    auto load_stage = [&](int s) {
        const uint32_t sb = smb + (uint32_t)(s & 1) * STAGE_B;
        const int k0 = s * 32;
        #pragma unroll
        for (int tile = 0; tile < 4; tile++) {
            const __nv_bfloat16* sp = src[tile];
            const int rb = (tile < 2) ? m0 : n0;
            #pragma unroll
            for (int i = 0; i < 2; i++) {
                int chunk = i * 256 + t;
                int row = chunk >> 2, cc = chunk & 3;
                cp_async16(sb + tile * TILE_B + row * 80 + cc * 16,
                           sp + (size_t)(rb + row) * KMAT + k0 + cc * 8);
            }
        }
        CP_COMMIT();
    };

    load_stage(0);
    for (int s = 0; s < S; s++) {
        if (s + 1 < S) { load_stage(s + 1); CP_WAIT(1); }
        else           { CP_WAIT(0); }
        __syncthreads();

        const uint32_t base = smb + (uint32_t)(s & 1) * STAGE_B;
        #pragma unroll
        for (int ks = 0; ks < 2; ks++) {
            uint32_t ah[2][4], al[2][4];
            #pragma unroll
            for (int mt = 0; mt < 2; mt++) {
                uint32_t off = (uint32_t)((wm * 32 + mt * 16 + ar) * 80
                                          + (ks * 16 + ac) * 2);
                ldsm4(ah[mt], base + off);
                ldsm4(al[mt], base + TILE_B + off);
            }
            uint32_t bh[16], bl[16];
            #pragma unroll
            for (int p = 0; p < 4; p++) {
                uint32_t off = (uint32_t)((wn * 64 + p * 16 + br) * 80
                                          + (ks * 16 + bc) * 2);
                ldsm4(&bh[p * 4], base + 2 * TILE_B + off);
                ldsm4(&bl[p * 4], base + 3 * TILE_B + off);
            }
            #pragma unroll
            for (int mt = 0; mt < 2; mt++)
                #pragma unroll
                for (int nt = 0; nt < 8; nt++) {
                    const int bi = (nt >> 1) * 4 + (nt & 1) * 2;
                    mma16816(acc[mt][nt], ah[mt], bh[bi], bh[bi + 1]);
                    mma16816(acc[mt][nt], ah[mt], bl[bi], bl[bi + 1]);
                    mma16816(acc[mt][nt], al[mt], bh[bi], bh[bi + 1]);
                }
        }
        __syncthreads();
    }

    // ------------------------- epilogue -------------------------
    // acc[mt][nt]: c0,c1 at (m, n),(m, n+1); c2,c3 at (m+8, n),(m+8, n+1)
    // m = m0 + wm*32 + mt*16 + lane/4 ; n = n0 + wn*64 + nt*8 + 2*(lane&3)
    const int mrow = m0 + wm * 32 + (lane >> 2);
    const int ncol = wn * 64 + (lane & 3) * 2;

    if (EPI == 0) {
        const int g = n0 >> 8;
        #pragma unroll
        for (int mt = 0; mt < 2; mt++) {
            #pragma unroll
            for (int nt = 0; nt < 8; nt++) {
                const int m  = mrow + mt * 16;
                const int ch = ((n0 + ncol) & 255) + nt * 8;
                float v0 = acc[mt][nt][0] + bias[(ch + 0) * 4 + g];
                float v1 = acc[mt][nt][1] + bias[(ch + 1) * 4 + g];
                float v2 = acc[mt][nt][2] + bias[(ch + 0) * 4 + g];
                float v3 = acc[mt][nt][3] + bias[(ch + 1) * 4 + g];
                if (g < 3) {
                    float* dst = (g == 0) ? g_q : (g == 1) ? g_k : g_v;
                    *(float2*)&dst[(size_t)m * 256 + ch]       = make_float2(v0, v1);
                    *(float2*)&dst[(size_t)(m + 8) * 256 + ch] = make_float2(v2, v3);
                } else {
                    __nv_bfloat16 h0, l0, h1, l1;
                    split_bf16(v0, h0, l0); split_bf16(v1, h1, l1);
                    *(__nv_bfloat162*)&g_chh[(size_t)m * 256 + ch] = __nv_bfloat162(h0, h1);
                    *(__nv_bfloat162*)&g_chl[(size_t)m * 256 + ch] = __nv_bfloat162(l0, l1);
                    split_bf16(v2, h0, l0); split_bf16(v3, h1, l1);
                    *(__nv_bfloat162*)&g_chh[(size_t)(m + 8) * 256 + ch] = __nv_bfloat162(h0, h1);
                    *(__nv_bfloat162*)&g_chl[(size_t)(m + 8) * 256 + ch] = __nv_bfloat162(l0, l1);
                }
            }
        }
    } else if (EPI == 1) {
        #pragma unroll
        for (int mt = 0; mt < 2; mt++)
            #pragma unroll
            for (int nt = 0; nt < 8; nt++) {
                const int m = mrow + mt * 16;
                const int n = ncol + nt * 8;          // N = 128, n0 = 0
                float v0 = fmaxf(acc[mt][nt][0] + bias[n],     0.f);
                float v1 = fmaxf(acc[mt][nt][1] + bias[n + 1], 0.f);
                float v2 = fmaxf(acc[mt][nt][2] + bias[n],     0.f);
                float v3 = fmaxf(acc[mt][nt][3] + bias[n + 1], 0.f);
                __nv_bfloat16 h0, l0, h1, l1;
                split_bf16(v0, h0, l0); split_bf16(v1, h1, l1);
                *(__nv_bfloat162*)&g_th[(size_t)m * 128 + n] = __nv_bfloat162(h0, h1);
                *(__nv_bfloat162*)&g_tl[(size_t)m * 128 + n] = __nv_bfloat162(l0, l1);
                split_bf16(v2, h0, l0); split_bf16(v3, h1, l1);
                *(__nv_bfloat162*)&g_th[(size_t)(m + 8) * 128 + n] = __nv_bfloat162(h0, h1);
                *(__nv_bfloat162*)&g_tl[(size_t)(m + 8) * 128 + n] = __nv_bfloat162(l0, l1);
            }
    } else if (EPI == 2) {
        #pragma unroll
        for (int mt = 0; mt < 2; mt++)
            #pragma unroll
            for (int nt = 0; nt < 8; nt++) {
                const int m = mrow + mt * 16;
                const int n = n0 + ncol + nt * 8;
                float v0 = 1.f / (1.f + expf(-(acc[mt][nt][0] + bias[n])));
                float v1 = 1.f / (1.f + expf(-(acc[mt][nt][1] + bias[n + 1])));
                float v2 = 1.f / (1.f + expf(-(acc[mt][nt][2] + bias[n])));
                float v3 = 1.f / (1.f + expf(-(acc[mt][nt][3] + bias[n + 1])));
                *(float2*)&g_gate[(size_t)m * 256 + n]       = make_float2(v0, v1);
                *(float2*)&g_gate[(size_t)(m + 8) * 256 + n] = make_float2(v2, v3);
            }
    } else { // EPI == 3: bias + smem transpose + coalesced NCHW store
        float* smT = (float*)sm;                  // [128 n][stride 132 m]
        const int ml = mrow - m0;
        #pragma unroll
        for (int mt = 0; mt < 2; mt++)
            #pragma unroll
            for (int nt = 0; nt < 8; nt++) {
                const int n = ncol + nt * 8;      // local n (0..127)
                smT[(n)     * 132 + ml + mt * 16]     = acc[mt][nt][0] + bias[n0 + n];
                smT[(n + 1) * 132 + ml + mt * 16]     = acc[mt][nt][1] + bias[n0 + n + 1];
                smT[(n)     * 132 + ml + mt * 16 + 8] = acc[mt][nt][2] + bias[n0 + n];
                smT[(n + 1) * 132 + ml + mt * 16 + 8] = acc[mt][nt][3] + bias[n0 + n + 1];
            }
        __syncthreads();
        const int nl = t >> 1, half = t & 1;
        const int bi = m0 >> 12, hw0 = m0 & 4095;
        float* orow = outp + ((size_t)(bi * 256 + n0 + nl)) * 4096 + hw0 + half * 64;
        #pragma unroll
        for (int i = 0; i < 16; i++)
            *(float4*)&orow[i * 4] = *(float4*)&smT[nl * 132 + half * 64 + i * 4];
    }
}

// ---------------------------------------------------------------------------
// Kernel: 3x3 local-window attention + gate; writes bf16 hi/lo for proj GEMM
// ---------------------------------------------------------------------------
__global__ void __launch_bounds__(256) attn_kernel()
{
    const int pos  = blockIdx.x;
    const int head = threadIdx.x >> 5;
    const int lane = threadIdx.x & 31;
    const int hw = pos & 4095;
    const int iy = hw >> 6, ix = hw & 63;
    const int ch = head * HD_ + lane;
    const size_t base = (size_t)pos * C_ + ch;

    const float q = g_q[base];
    float logit[9], vv[9];
    #pragma unroll
    for (int j = 0; j < 9; j++) {
        int dy = j / 3 - 1, dx = j % 3 - 1;
        int ny = iy + dy, nx = ix + dx;
        float p = 0.f, val = 0.f;
        if (ny >= 0 && ny < H_ && nx >= 0 && nx < W_) {
            int npos = pos + dy * 64 + dx;
            size_t nb = (size_t)npos * C_ + ch;
            p   = q * g_k[nb];
            val = g_v[nb];
        }
        #pragma unroll
        for (int off = 16; off; off >>= 1)
            p += __shfl_xor_sync(0xffffffffu, p, off);
        logit[j] = p * 0.17677669529663687f;
        vv[j] = val;
    }

    float mx = logit[0];
    #pragma unroll
    for (int j = 1; j < 9; j++) mx = fmaxf(mx, logit[j]);
    float e[9], ssum = 0.f;
    #pragma unroll
    for (int j = 0; j < 9; j++) { e[j] = __expf(logit[j] - mx); ssum += e[j]; }
    const float inv = 1.f / ssum;
    float o = 0.f;
    #pragma unroll
    for (int j = 0; j < 9; j++) o += e[j] * inv * vv[j];

    const float r = o * (1.f + g_gate[base]);
    __nv_bfloat16 hi, lo;
    split_bf16(r, hi, lo);
    g_ath[base] = hi;
    g_atl[base] = lo;
}

// ---------------------------------------------------------------------------
extern "C" void kernel_launch(void* const* d_in, const int* in_sizes, int n_in,
                              void* d_out, int out_size)
{
    const float* x     = (const float*)d_in[0];
    const float* W_qkv = (const float*)d_in[1];
    const float* b_qkv = (const float*)d_in[2];
    const float* W1    = (const float*)d_in[3];
    const float* b1    = (const float*)d_in[4];
    const float* W2    = (const float*)d_in[5];
    const float* b2    = (const float*)d_in[6];
    const float* Wp    = (const float*)d_in[7];
    const float* bp    = (const float*)d_in[8];
    float* out = (float*)d_out;

    cudaFuncSetAttribute(mma_gemm<0, 0,  8, 256>, cudaFuncAttributeMaxDynamicSharedMemorySize, SMEM_SZ);
    cudaFuncSetAttribute(mma_gemm<1, 2, 10, 256>, cudaFuncAttributeMaxDynamicSharedMemorySize, SMEM_SZ);
    cudaFuncSetAttribute(mma_gemm<2, 4, 12, 128>, cudaFuncAttributeMaxDynamicSharedMemorySize, SMEM_SZ);
    cudaFuncSetAttribute(mma_gemm<3, 6, 14, 256>, cudaFuncAttributeMaxDynamicSharedMemorySize, SMEM_SZ);

    // 1) weight conversion (bf16 hi/lo, QKV permuted) + avg pool
    convert_weights<<<1536, 256>>>(W_qkv, W1, W2, Wp);
    avgpool_kernel<<<dim3(H_, C_ / 32, B_), 256>>>(x);

    // 2) QKV GEMM: [32768,1024] = y @ Wqkv^T  -> q/k/v fp32, ch bf16
    mma_gemm<0, 0, 8, 256><<<dim3(8, 256), 256, SMEM_SZ>>>(b_qkv, nullptr);

    // 3) gate hidden: relu(ch @ W1^T + b1) -> th/tl  (N=128)
    mma_gemm<1, 2, 10, 256><<<dim3(1, 256), 256, SMEM_SZ>>>(b1, nullptr);

    // 4) gate: sigmoid(t @ W2^T + b2) -> g_gate  (N=256, K=128)
    mma_gemm<2, 4, 12, 128><<<dim3(2, 256), 256, SMEM_SZ>>>(b2, nullptr);

    // 5) local attention + (1+g) -> ath/atl bf16
    attn_kernel<<<M_, 256>>>();

    // 6) projection + bias + NCHW store -> d_out
    mma_gemm<3, 6, 14, 256><<<dim3(2, 256), 256, SMEM_SZ>>>(bp, out);
}

// round 7
// speedup vs baseline: 2.7838x; 1.0921x over previous
#include <cuda_runtime.h>
#include <cuda_bf16.h>
#include <cuda_fp16.h>
#include <math.h>
#include <stdint.h>

#define B_    8
#define C_    256
#define H_    64
#define W_    64
#define M_    32768
#define NH_   8
#define HD_   32

// ---------------------------------------------------------------------------
// Scratch buffers (__device__ globals: allocation-free)
// ---------------------------------------------------------------------------
__device__ __half g_q  [M_*C_];
__device__ __half g_k  [M_*C_];
__device__ __half g_v  [M_*C_];
__device__ float  g_gate[M_*C_];

__device__ __nv_bfloat16 g_yh [M_*C_],  g_yl [M_*C_];
__device__ __nv_bfloat16 g_chh[M_*C_],  g_chl[M_*C_];
__device__ __nv_bfloat16 g_th [M_*128], g_tl [M_*128];
__device__ __nv_bfloat16 g_ath[M_*C_],  g_atl[M_*C_];
__device__ __nv_bfloat16 g_wqh[1024*256], g_wql[1024*256];
__device__ __nv_bfloat16 g_w1h[128*256],  g_w1l[128*256];
__device__ __nv_bfloat16 g_w2h[256*128],  g_w2l[256*128];
__device__ __nv_bfloat16 g_wph[256*256],  g_wpl[256*256];

__device__ __forceinline__ const __nv_bfloat16* bf_buf(int id) {
    switch (id) {
        case 0:  return g_yh;  case 1:  return g_yl;
        case 2:  return g_chh; case 3:  return g_chl;
        case 4:  return g_th;  case 5:  return g_tl;
        case 6:  return g_ath; case 7:  return g_atl;
        case 8:  return g_wqh; case 9:  return g_wql;
        case 10: return g_w1h; case 11: return g_w1l;
        case 12: return g_w2h; case 13: return g_w2l;
        case 14: return g_wph; case 15: return g_wpl;
    }
    return nullptr;
}

__device__ __forceinline__ void split_bf16(float v, __nv_bfloat16& h, __nv_bfloat16& l) {
    h = __float2bfloat16(v);
    l = __float2bfloat16(v - __bfloat162float(h));
}

// ---------------------------------------------------------------------------
// sm_80-compatible async-copy / ldmatrix / mma.sync helpers
// ---------------------------------------------------------------------------
__device__ __forceinline__ uint32_t smem_to_u32(const void* p) {
    uint32_t a;
    asm("{ .reg .u64 t; cvta.to.shared.u64 t, %1; cvt.u32.u64 %0, t; }"
        : "=r"(a) : "l"(p));
    return a;
}
__device__ __forceinline__ void cp_async16(uint32_t sa, const void* g) {
    asm volatile("cp.async.cg.shared.global [%0], [%1], 16;" :: "r"(sa), "l"(g));
}
#define CP_COMMIT() asm volatile("cp.async.commit_group;" ::: "memory")
#define CP_WAIT(n)  asm volatile("cp.async.wait_group %0;" :: "n"(n) : "memory")

__device__ __forceinline__ void ldsm4(uint32_t* r, uint32_t a) {
    asm volatile("ldmatrix.sync.aligned.m8n8.x4.shared.b16 {%0,%1,%2,%3}, [%4];"
        : "=r"(r[0]), "=r"(r[1]), "=r"(r[2]), "=r"(r[3]) : "r"(a));
}
__device__ __forceinline__ void mma16816(float* c, const uint32_t* a,
                                         uint32_t b0, uint32_t b1) {
    asm volatile(
        "mma.sync.aligned.m16n8k16.row.col.f32.bf16.bf16.f32 "
        "{%0,%1,%2,%3}, {%4,%5,%6,%7}, {%8,%9}, {%0,%1,%2,%3};"
        : "+f"(c[0]), "+f"(c[1]), "+f"(c[2]), "+f"(c[3])
        : "r"(a[0]), "r"(a[1]), "r"(a[2]), "r"(a[3]), "r"(b0), "r"(b1));
}

// Swizzled tile layout: [128 rows][32 bf16] = 64B/row = 4 chunks of 16B.
// phys chunk = row*4 + (c ^ ((row>>1)&3))  — conflict-free for cp.async
// writes (4 consecutive-thread chunks per row) and 8-row ldmatrix reads.
__device__ __forceinline__ uint32_t sw_off(int row, int c) {
    return (uint32_t)((row * 4 + (c ^ ((row >> 1) & 3))) << 4);
}

// ---------------------------------------------------------------------------
// Kernel 1: 3x3 avg pool + transpose to [pos, C], output split into bf16 hi/lo
// ---------------------------------------------------------------------------
__global__ void __launch_bounds__(256) avgpool_kernel(const float* __restrict__ x)
{
    const int h  = blockIdx.x;
    const int c0 = blockIdx.y * 32;
    const int b  = blockIdx.z;
    __shared__ float s[96][65];

    const int t = threadIdx.x;
    #pragma unroll 4
    for (int ri = 0; ri < 24; ri++) {
        int rowid = ri * 4 + (t >> 6);
        int w  = t & 63;
        int cc = rowid / 3;
        int dh = rowid - cc * 3;
        int hh = h + dh - 1;
        float v = 0.f;
        if (hh >= 0 && hh < H_)
            v = x[(((size_t)b * C_ + c0 + cc) * H_ + hh) * W_ + w];
        s[rowid][w] = v;
    }
    __syncthreads();

    const int cc = t & 31;
    const int wq = t >> 5;
    #pragma unroll
    for (int wi = 0; wi < 8; wi++) {
        int w = wi * 8 + wq;
        float sum = 0.f;
        #pragma unroll
        for (int dh = 0; dh < 3; dh++) {
            const float* row = s[cc * 3 + dh];
            #pragma unroll
            for (int dw = -1; dw <= 1; dw++) {
                int w2 = w + dw;
                if (w2 >= 0 && w2 < W_) sum += row[w2];
            }
        }
        size_t pos = (size_t)b * 4096 + h * 64 + w;
        __nv_bfloat16 hi, lo;
        split_bf16(sum * (1.f / 9.f), hi, lo);
        g_yh[pos * C_ + c0 + cc] = hi;
        g_yl[pos * C_ + c0 + cc] = lo;
    }
}

// ---------------------------------------------------------------------------
// Kernel: weight conversion to bf16 hi/lo (+ QKV column permutation)
// ---------------------------------------------------------------------------
__global__ void __launch_bounds__(256) convert_weights(
    const float* __restrict__ Wq, const float* __restrict__ W1,
    const float* __restrict__ W2, const float* __restrict__ Wp)
{
    int i = blockIdx.x * 256 + threadIdx.x;
    if (i < 262144) {
        int n = i >> 8, kk = i & 255;
        int orig = (n & 255) * 4 + (n >> 8);
        split_bf16(Wq[orig * 256 + kk], g_wqh[i], g_wql[i]);
    } else if (i < 294912) {
        int j = i - 262144;
        split_bf16(W1[j], g_w1h[j], g_w1l[j]);
    } else if (i < 327680) {
        int j = i - 294912;
        split_bf16(W2[j], g_w2h[j], g_w2l[j]);
    } else if (i < 393216) {
        int j = i - 327680;
        split_bf16(Wp[j], g_wph[j], g_wpl[j]);
    }
}

// ---------------------------------------------------------------------------
// mma.sync bf16 GEMM with 3-product precision splitting.
// C[M,N] = A[M,K] @ W[N,K]^T, fp32 accum.  BM=BN=128, BK=32, 256 threads.
// 3-stage cp.async pipeline, swizzled 32KB stages (Ah|Al|Bh|Bl 8KB each),
// ONE __syncthreads per stage. __launch_bounds__(256,2) -> 2 CTAs/SM.
// EPI: 0 QKV split (q/k/v fp16 + ch bf16)  1 relu->bf16
//      2 sigmoid->gate                      3 bias+NCHW store
// ---------------------------------------------------------------------------
#define TILE_B   8192           // 128 rows * 64B swizzled
#define STAGE_B  (4 * TILE_B)   // 32768
#define SMEM_SZ  (3 * STAGE_B)  // 98304

template<int EPI, int AID, int BID, int KMAT>
__global__ void __launch_bounds__(256, 2) mma_gemm(
    const float* __restrict__ bias, float* __restrict__ outp)
{
    extern __shared__ char sm[];
    const uint32_t smb = smem_to_u32(sm);
    const int t = threadIdx.x;
    const int wid = t >> 5, lane = t & 31;
    const int wm = wid & 3, wn = wid >> 2;
    const int m0 = blockIdx.y * 128;
    const int n0 = blockIdx.x * 128;
    constexpr int S = KMAT / 32;

    const __nv_bfloat16* src[4] = { bf_buf(AID), bf_buf(AID + 1),
                                    bf_buf(BID), bf_buf(BID + 1) };

    float acc[2][8][4];
    #pragma unroll
    for (int i = 0; i < 2; i++)
        #pragma unroll
        for (int j = 0; j < 8; j++)
            #pragma unroll
            for (int q = 0; q < 4; q++) acc[i][j][q] = 0.f;

    // ldmatrix lane->row/chunk mapping (fragment order identical to Round 5)
    const int ar = lane & 15;            // A row within 16-row tile
    const int ahc = lane >> 4;           // A chunk half (k0 / k8)
    const int br = (lane & 7) + ((lane >> 4) << 3);   // B row
    const int bhc = (lane >> 3) & 1;     // B chunk half

    auto load_stage = [&](int s) {
        const uint32_t sb = smb + (uint32_t)(s % 3) * STAGE_B;
        const int k0 = s * 32;
        #pragma unroll
        for (int tile = 0; tile < 4; tile++) {
            const __nv_bfloat16* sp = src[tile];
            const int rb = (tile < 2) ? m0 : n0;
            #pragma unroll
            for (int i = 0; i < 2; i++) {
                int chunk = i * 256 + t;
                int row = chunk >> 2, cc = chunk & 3;
                cp_async16(sb + tile * TILE_B + sw_off(row, cc),
                           sp + (size_t)(rb + row) * KMAT + k0 + cc * 8);
            }
        }
    };

    load_stage(0); CP_COMMIT();
    load_stage(1); CP_COMMIT();
    CP_WAIT(1);
    __syncthreads();

    for (int s = 0; s < S; s++) {
        if (s + 2 < S) load_stage(s + 2);
        CP_COMMIT();

        const uint32_t base = smb + (uint32_t)(s % 3) * STAGE_B;
        #pragma unroll
        for (int ks = 0; ks < 2; ks++) {
            uint32_t ah[2][4], al[2][4];
            #pragma unroll
            for (int mt = 0; mt < 2; mt++) {
                uint32_t off = sw_off(wm * 32 + mt * 16 + ar, ks * 2 + ahc);
                ldsm4(ah[mt], base + off);
                ldsm4(al[mt], base + TILE_B + off);
            }
            uint32_t bh[16], bl[16];
            #pragma unroll
            for (int p = 0; p < 4; p++) {
                uint32_t off = sw_off(wn * 64 + p * 16 + br, ks * 2 + bhc);
                ldsm4(&bh[p * 4], base + 2 * TILE_B + off);
                ldsm4(&bl[p * 4], base + 3 * TILE_B + off);
            }
            #pragma unroll
            for (int mt = 0; mt < 2; mt++)
                #pragma unroll
                for (int nt = 0; nt < 8; nt++) {
                    const int bi = (nt >> 1) * 4 + (nt & 1) * 2;
                    mma16816(acc[mt][nt], ah[mt], bh[bi], bh[bi + 1]);
                    mma16816(acc[mt][nt], ah[mt], bl[bi], bl[bi + 1]);
                    mma16816(acc[mt][nt], al[mt], bh[bi], bh[bi + 1]);
                }
        }

        CP_WAIT(1);
        __syncthreads();
    }

    // ------------------------- epilogue -------------------------
    // acc[mt][nt]: c0,c1 at (m, n),(m, n+1); c2,c3 at (m+8, n),(m+8, n+1)
    // m = m0 + wm*32 + mt*16 + lane/4 ; n = n0 + wn*64 + nt*8 + 2*(lane&3)
    const int mrow = m0 + wm * 32 + (lane >> 2);
    const int ncol = wn * 64 + (lane & 3) * 2;

    if (EPI == 0) {
        const int g = n0 >> 8;
        #pragma unroll
        for (int mt = 0; mt < 2; mt++) {
            #pragma unroll
            for (int nt = 0; nt < 8; nt++) {
                const int m  = mrow + mt * 16;
                const int ch = ((n0 + ncol) & 255) + nt * 8;
                float v0 = acc[mt][nt][0] + bias[(ch + 0) * 4 + g];
                float v1 = acc[mt][nt][1] + bias[(ch + 1) * 4 + g];
                float v2 = acc[mt][nt][2] + bias[(ch + 0) * 4 + g];
                float v3 = acc[mt][nt][3] + bias[(ch + 1) * 4 + g];
                if (g < 3) {
                    __half* dst = (g == 0) ? g_q : (g == 1) ? g_k : g_v;
                    *(__half2*)&dst[(size_t)m * 256 + ch]       = __floats2half2_rn(v0, v1);
                    *(__half2*)&dst[(size_t)(m + 8) * 256 + ch] = __floats2half2_rn(v2, v3);
                } else {
                    __nv_bfloat16 h0, l0, h1, l1;
                    split_bf16(v0, h0, l0); split_bf16(v1, h1, l1);
                    *(__nv_bfloat162*)&g_chh[(size_t)m * 256 + ch] = __nv_bfloat162(h0, h1);
                    *(__nv_bfloat162*)&g_chl[(size_t)m * 256 + ch] = __nv_bfloat162(l0, l1);
                    split_bf16(v2, h0, l0); split_bf16(v3, h1, l1);
                    *(__nv_bfloat162*)&g_chh[(size_t)(m + 8) * 256 + ch] = __nv_bfloat162(h0, h1);
                    *(__nv_bfloat162*)&g_chl[(size_t)(m + 8) * 256 + ch] = __nv_bfloat162(l0, l1);
                }
            }
        }
    } else if (EPI == 1) {
        #pragma unroll
        for (int mt = 0; mt < 2; mt++)
            #pragma unroll
            for (int nt = 0; nt < 8; nt++) {
                const int m = mrow + mt * 16;
                const int n = ncol + nt * 8;          // N = 128, n0 = 0
                float v0 = fmaxf(acc[mt][nt][0] + bias[n],     0.f);
                float v1 = fmaxf(acc[mt][nt][1] + bias[n + 1], 0.f);
                float v2 = fmaxf(acc[mt][nt][2] + bias[n],     0.f);
                float v3 = fmaxf(acc[mt][nt][3] + bias[n + 1], 0.f);
                __nv_bfloat16 h0, l0, h1, l1;
                split_bf16(v0, h0, l0); split_bf16(v1, h1, l1);
                *(__nv_bfloat162*)&g_th[(size_t)m * 128 + n] = __nv_bfloat162(h0, h1);
                *(__nv_bfloat162*)&g_tl[(size_t)m * 128 + n] = __nv_bfloat162(l0, l1);
                split_bf16(v2, h0, l0); split_bf16(v3, h1, l1);
                *(__nv_bfloat162*)&g_th[(size_t)(m + 8) * 128 + n] = __nv_bfloat162(h0, h1);
                *(__nv_bfloat162*)&g_tl[(size_t)(m + 8) * 128 + n] = __nv_bfloat162(l0, l1);
            }
    } else if (EPI == 2) {
        #pragma unroll
        for (int mt = 0; mt < 2; mt++)
            #pragma unroll
            for (int nt = 0; nt < 8; nt++) {
                const int m = mrow + mt * 16;
                const int n = n0 + ncol + nt * 8;
                float v0 = 1.f / (1.f + expf(-(acc[mt][nt][0] + bias[n])));
                float v1 = 1.f / (1.f + expf(-(acc[mt][nt][1] + bias[n + 1])));
                float v2 = 1.f / (1.f + expf(-(acc[mt][nt][2] + bias[n])));
                float v3 = 1.f / (1.f + expf(-(acc[mt][nt][3] + bias[n + 1])));
                *(float2*)&g_gate[(size_t)m * 256 + n]       = make_float2(v0, v1);
                *(float2*)&g_gate[(size_t)(m + 8) * 256 + n] = make_float2(v2, v3);
            }
    } else { // EPI == 3: bias + smem transpose + coalesced NCHW store
        float* smT = (float*)sm;                  // [128 n][stride 132 m]
        const int ml = mrow - m0;
        #pragma unroll
        for (int mt = 0; mt < 2; mt++)
            #pragma unroll
            for (int nt = 0; nt < 8; nt++) {
                const int n = ncol + nt * 8;      // local n (0..127)
                smT[(n)     * 132 + ml + mt * 16]     = acc[mt][nt][0] + bias[n0 + n];
                smT[(n + 1) * 132 + ml + mt * 16]     = acc[mt][nt][1] + bias[n0 + n + 1];
                smT[(n)     * 132 + ml + mt * 16 + 8] = acc[mt][nt][2] + bias[n0 + n];
                smT[(n + 1) * 132 + ml + mt * 16 + 8] = acc[mt][nt][3] + bias[n0 + n + 1];
            }
        __syncthreads();
        const int nl = t >> 1, half = t & 1;
        const int bi = m0 >> 12, hw0 = m0 & 4095;
        float* orow = outp + ((size_t)(bi * 256 + n0 + nl)) * 4096 + hw0 + half * 64;
        #pragma unroll
        for (int i = 0; i < 16; i++)
            *(float4*)&orow[i * 4] = *(float4*)&smT[nl * 132 + half * 64 + i * 4];
    }
}

// ---------------------------------------------------------------------------
// Kernel: 3x3 local-window attention + gate; q/k/v fp16, writes bf16 hi/lo
// ---------------------------------------------------------------------------
__global__ void __launch_bounds__(256) attn_kernel()
{
    const int pos  = blockIdx.x;
    const int head = threadIdx.x >> 5;
    const int lane = threadIdx.x & 31;
    const int hw = pos & 4095;
    const int iy = hw >> 6, ix = hw & 63;
    const int ch = head * HD_ + lane;
    const size_t base = (size_t)pos * C_ + ch;

    const float q = __half2float(g_q[base]);
    float logit[9], vv[9];
    #pragma unroll
    for (int j = 0; j < 9; j++) {
        int dy = j / 3 - 1, dx = j % 3 - 1;
        int ny = iy + dy, nx = ix + dx;
        float p = 0.f, val = 0.f;
        if (ny >= 0 && ny < H_ && nx >= 0 && nx < W_) {
            int npos = pos + dy * 64 + dx;
            size_t nb = (size_t)npos * C_ + ch;
            p   = q * __half2float(g_k[nb]);
            val = __half2float(g_v[nb]);
        }
        #pragma unroll
        for (int off = 16; off; off >>= 1)
            p += __shfl_xor_sync(0xffffffffu, p, off);
        logit[j] = p * 0.17677669529663687f;
        vv[j] = val;
    }

    float mx = logit[0];
    #pragma unroll
    for (int j = 1; j < 9; j++) mx = fmaxf(mx, logit[j]);
    float e[9], ssum = 0.f;
    #pragma unroll
    for (int j = 0; j < 9; j++) { e[j] = __expf(logit[j] - mx); ssum += e[j]; }
    const float inv = 1.f / ssum;
    float o = 0.f;
    #pragma unroll
    for (int j = 0; j < 9; j++) o += e[j] * inv * vv[j];

    const float r = o * (1.f + g_gate[base]);
    __nv_bfloat16 hi, lo;
    split_bf16(r, hi, lo);
    g_ath[base] = hi;
    g_atl[base] = lo;
}

// ---------------------------------------------------------------------------
extern "C" void kernel_launch(void* const* d_in, const int* in_sizes, int n_in,
                              void* d_out, int out_size)
{
    const float* x     = (const float*)d_in[0];
    const float* W_qkv = (const float*)d_in[1];
    const float* b_qkv = (const float*)d_in[2];
    const float* W1    = (const float*)d_in[3];
    const float* b1    = (const float*)d_in[4];
    const float* W2    = (const float*)d_in[5];
    const float* b2    = (const float*)d_in[6];
    const float* Wp    = (const float*)d_in[7];
    const float* bp    = (const float*)d_in[8];
    float* out = (float*)d_out;

    cudaFuncSetAttribute(mma_gemm<0, 0,  8, 256>, cudaFuncAttributeMaxDynamicSharedMemorySize, SMEM_SZ);
    cudaFuncSetAttribute(mma_gemm<1, 2, 10, 256>, cudaFuncAttributeMaxDynamicSharedMemorySize, SMEM_SZ);
    cudaFuncSetAttribute(mma_gemm<2, 4, 12, 128>, cudaFuncAttributeMaxDynamicSharedMemorySize, SMEM_SZ);
    cudaFuncSetAttribute(mma_gemm<3, 6, 14, 256>, cudaFuncAttributeMaxDynamicSharedMemorySize, SMEM_SZ);

    // 1) weight conversion (bf16 hi/lo, QKV permuted) + avg pool
    convert_weights<<<1536, 256>>>(W_qkv, W1, W2, Wp);
    avgpool_kernel<<<dim3(H_, C_ / 32, B_), 256>>>(x);

    // 2) QKV GEMM: [32768,1024] = y @ Wqkv^T  -> q/k/v fp16, ch bf16
    mma_gemm<0, 0, 8, 256><<<dim3(8, 256), 256, SMEM_SZ>>>(b_qkv, nullptr);

    // 3) gate hidden: relu(ch @ W1^T + b1) -> th/tl  (N=128)
    mma_gemm<1, 2, 10, 256><<<dim3(1, 256), 256, SMEM_SZ>>>(b1, nullptr);

    // 4) gate: sigmoid(t @ W2^T + b2) -> g_gate  (N=256, K=128)
    mma_gemm<2, 4, 12, 128><<<dim3(2, 256), 256, SMEM_SZ>>>(b2, nullptr);

    // 5) local attention + (1+g) -> ath/atl bf16
    attn_kernel<<<M_, 256>>>();

    // 6) projection + bias + NCHW store -> d_out
    mma_gemm<3, 6, 14, 256><<<dim3(2, 256), 256, SMEM_SZ>>>(bp, out);
}

// round 8
// speedup vs baseline: 2.9975x; 1.0768x over previous
#include <cuda_runtime.h>
#include <cuda_bf16.h>
#include <cuda_fp16.h>
#include <math.h>
#include <stdint.h>

#define B_    8
#define C_    256
#define H_    64
#define W_    64
#define M_    32768
#define NH_   8
#define HD_   32

// ---------------------------------------------------------------------------
// Scratch buffers (__device__ globals: allocation-free)
// ---------------------------------------------------------------------------
__device__ __half g_q  [M_*C_];
__device__ __half g_k  [M_*C_];
__device__ __half g_v  [M_*C_];
__device__ float  g_gate[M_*C_];

__device__ __nv_bfloat16 g_yh [M_*C_],  g_yl [M_*C_];
__device__ __nv_bfloat16 g_chh[M_*C_];                 // single-precision path
__device__ __nv_bfloat16 g_th [M_*128];
__device__ __nv_bfloat16 g_ath[M_*C_],  g_atl[M_*C_];
__device__ __nv_bfloat16 g_wqh[1024*256], g_wql[1024*256];
__device__ __nv_bfloat16 g_w1h[128*256];
__device__ __nv_bfloat16 g_w2h[256*128];
__device__ __nv_bfloat16 g_wph[256*256],  g_wpl[256*256];

// id -> {A_hi, A_lo, B_hi, B_lo} selection (lo may be unused for PROD=1)
__device__ __forceinline__ const __nv_bfloat16* bf_buf(int id) {
    switch (id) {
        case 0:  return g_yh;  case 1:  return g_yl;
        case 2:  return g_chh;
        case 4:  return g_th;
        case 6:  return g_ath; case 7:  return g_atl;
        case 8:  return g_wqh; case 9:  return g_wql;
        case 10: return g_w1h;
        case 12: return g_w2h;
        case 14: return g_wph; case 15: return g_wpl;
    }
    return nullptr;
}

__device__ __forceinline__ void split_bf16(float v, __nv_bfloat16& h, __nv_bfloat16& l) {
    h = __float2bfloat16(v);
    l = __float2bfloat16(v - __bfloat162float(h));
}

// ---------------------------------------------------------------------------
// sm_80-compatible async-copy / ldmatrix / mma.sync helpers
// ---------------------------------------------------------------------------
__device__ __forceinline__ uint32_t smem_to_u32(const void* p) {
    uint32_t a;
    asm("{ .reg .u64 t; cvta.to.shared.u64 t, %1; cvt.u32.u64 %0, t; }"
        : "=r"(a) : "l"(p));
    return a;
}
__device__ __forceinline__ void cp_async16(uint32_t sa, const void* g) {
    asm volatile("cp.async.cg.shared.global [%0], [%1], 16;" :: "r"(sa), "l"(g));
}
#define CP_COMMIT() asm volatile("cp.async.commit_group;" ::: "memory")
#define CP_WAIT(n)  asm volatile("cp.async.wait_group %0;" :: "n"(n) : "memory")

__device__ __forceinline__ void ldsm4(uint32_t* r, uint32_t a) {
    asm volatile("ldmatrix.sync.aligned.m8n8.x4.shared.b16 {%0,%1,%2,%3}, [%4];"
        : "=r"(r[0]), "=r"(r[1]), "=r"(r[2]), "=r"(r[3]) : "r"(a));
}
__device__ __forceinline__ void mma16816(float* c, const uint32_t* a,
                                         uint32_t b0, uint32_t b1) {
    asm volatile(
        "mma.sync.aligned.m16n8k16.row.col.f32.bf16.bf16.f32 "
        "{%0,%1,%2,%3}, {%4,%5,%6,%7}, {%8,%9}, {%0,%1,%2,%3};"
        : "+f"(c[0]), "+f"(c[1]), "+f"(c[2]), "+f"(c[3])
        : "r"(a[0]), "r"(a[1]), "r"(a[2]), "r"(a[3]), "r"(b0), "r"(b1));
}

// Swizzled tile layout: [128 rows][32 bf16] = 64B/row = 4 chunks of 16B.
__device__ __forceinline__ uint32_t sw_off(int row, int c) {
    return (uint32_t)((row * 4 + (c ^ ((row >> 1) & 3))) << 4);
}

// ---------------------------------------------------------------------------
// Kernel 1: 3x3 avg pool + transpose to [pos, C], output split into bf16 hi/lo
// ---------------------------------------------------------------------------
__global__ void __launch_bounds__(256) avgpool_kernel(const float* __restrict__ x)
{
    const int h  = blockIdx.x;
    const int c0 = blockIdx.y * 32;
    const int b  = blockIdx.z;
    __shared__ float s[96][65];

    const int t = threadIdx.x;
    #pragma unroll 4
    for (int ri = 0; ri < 24; ri++) {
        int rowid = ri * 4 + (t >> 6);
        int w  = t & 63;
        int cc = rowid / 3;
        int dh = rowid - cc * 3;
        int hh = h + dh - 1;
        float v = 0.f;
        if (hh >= 0 && hh < H_)
            v = x[(((size_t)b * C_ + c0 + cc) * H_ + hh) * W_ + w];
        s[rowid][w] = v;
    }
    __syncthreads();

    const int cc = t & 31;
    const int wq = t >> 5;
    #pragma unroll
    for (int wi = 0; wi < 8; wi++) {
        int w = wi * 8 + wq;
        float sum = 0.f;
        #pragma unroll
        for (int dh = 0; dh < 3; dh++) {
            const float* row = s[cc * 3 + dh];
            #pragma unroll
            for (int dw = -1; dw <= 1; dw++) {
                int w2 = w + dw;
                if (w2 >= 0 && w2 < W_) sum += row[w2];
            }
        }
        size_t pos = (size_t)b * 4096 + h * 64 + w;
        __nv_bfloat16 hi, lo;
        split_bf16(sum * (1.f / 9.f), hi, lo);
        g_yh[pos * C_ + c0 + cc] = hi;
        g_yl[pos * C_ + c0 + cc] = lo;
    }
}

// ---------------------------------------------------------------------------
// Kernel: weight conversion (QKV/proj hi+lo; gate weights hi only)
// ---------------------------------------------------------------------------
__global__ void __launch_bounds__(256) convert_weights(
    const float* __restrict__ Wq, const float* __restrict__ W1,
    const float* __restrict__ W2, const float* __restrict__ Wp)
{
    int i = blockIdx.x * 256 + threadIdx.x;
    if (i < 262144) {
        int n = i >> 8, kk = i & 255;
        int orig = (n & 255) * 4 + (n >> 8);
        split_bf16(Wq[orig * 256 + kk], g_wqh[i], g_wql[i]);
    } else if (i < 294912) {
        int j = i - 262144;
        g_w1h[j] = __float2bfloat16(W1[j]);
    } else if (i < 327680) {
        int j = i - 294912;
        g_w2h[j] = __float2bfloat16(W2[j]);
    } else if (i < 393216) {
        int j = i - 327680;
        split_bf16(Wp[j], g_wph[j], g_wpl[j]);
    }
}

// ---------------------------------------------------------------------------
// mma.sync bf16 GEMM, PROD = 3 (hi/lo precision split) or 1 (plain bf16).
// C[M,N] = A[M,K] @ W[N,K]^T, fp32 accum.  BM=BN=128, BK=32, 256 threads.
// 3-stage cp.async pipeline, swizzled tiles, one __syncthreads per stage.
// PROD==3 stage: Ah|Al|Bh|Bl (32KB). PROD==1 stage: Ah|Bh (16KB).
// EPI==0 (QKV): blocks with n0>=768 (the `chans` quarter) run single-product
// at runtime — the gate path is provably insensitive to bf16 rounding.
// EPI: 0 QKV split (q/k/v fp16 + ch bf16)  1 relu->bf16 (t)
//      2 sigmoid->gate                      3 bias+NCHW store
// ---------------------------------------------------------------------------
#define TILE_B   8192           // 128 rows * 64B swizzled

template<int EPI, int AID, int BID, int KMAT, int PROD>
__global__ void __launch_bounds__(256, 2) mma_gemm(
    const float* __restrict__ bias, float* __restrict__ outp)
{
    extern __shared__ char sm[];
    const uint32_t smb = smem_to_u32(sm);
    const int t = threadIdx.x;
    const int wid = t >> 5, lane = t & 31;
    const int wm = wid & 3, wn = wid >> 2;
    const int m0 = blockIdx.y * 128;
    const int n0 = blockIdx.x * 128;
    constexpr int S = KMAT / 32;
    constexpr int NTILES  = (PROD == 3) ? 4 : 2;
    constexpr int STAGE_B = NTILES * TILE_B;
    constexpr int BSLOT   = (PROD == 3) ? 2 : 1;

    // runtime precision flag (uniform per block)
    const bool full = (EPI == 0) ? (n0 < 768) : (PROD == 3);

    const __nv_bfloat16* src[4] = { bf_buf(AID), bf_buf(AID + 1),
                                    bf_buf(BID), bf_buf(BID + 1) };

    float acc[2][8][4];
    #pragma unroll
    for (int i = 0; i < 2; i++)
        #pragma unroll
        for (int j = 0; j < 8; j++)
            #pragma unroll
            for (int q = 0; q < 4; q++) acc[i][j][q] = 0.f;

    const int ar = lane & 15;
    const int ahc = lane >> 4;
    const int br = (lane & 7) + ((lane >> 4) << 3);
    const int bhc = (lane >> 3) & 1;

    auto load_stage = [&](int s) {
        const uint32_t sb = smb + (uint32_t)(s % 3) * STAGE_B;
        const int k0 = s * 32;
        #pragma unroll
        for (int tile = 0; tile < NTILES; tile++) {
            if (PROD == 3 && EPI == 0 && !full && (tile & 1)) continue; // skip lo
            const __nv_bfloat16* sp = (PROD == 3) ? src[tile]
                                                  : src[tile * 2];
            const int rb = (PROD == 3) ? ((tile < 2) ? m0 : n0)
                                       : ((tile == 0) ? m0 : n0);
            #pragma unroll
            for (int i = 0; i < 2; i++) {
                int chunk = i * 256 + t;
                int row = chunk >> 2, cc = chunk & 3;
                cp_async16(sb + tile * TILE_B + sw_off(row, cc),
                           sp + (size_t)(rb + row) * KMAT + k0 + cc * 8);
            }
        }
    };

    load_stage(0); CP_COMMIT();
    load_stage(1); CP_COMMIT();
    CP_WAIT(1);
    __syncthreads();

    for (int s = 0; s < S; s++) {
        if (s + 2 < S) load_stage(s + 2);
        CP_COMMIT();

        const uint32_t base = smb + (uint32_t)(s % 3) * STAGE_B;
        const uint32_t bbase = base + BSLOT * TILE_B;
        #pragma unroll
        for (int ks = 0; ks < 2; ks++) {
            uint32_t ah[2][4], al[2][4];
            #pragma unroll
            for (int mt = 0; mt < 2; mt++) {
                uint32_t off = sw_off(wm * 32 + mt * 16 + ar, ks * 2 + ahc);
                ldsm4(ah[mt], base + off);
                if (PROD == 3 && full) ldsm4(al[mt], base + TILE_B + off);
            }
            uint32_t bh[16], bl[16];
            #pragma unroll
            for (int p = 0; p < 4; p++) {
                uint32_t off = sw_off(wn * 64 + p * 16 + br, ks * 2 + bhc);
                ldsm4(&bh[p * 4], bbase + off);
                if (PROD == 3 && full) ldsm4(&bl[p * 4], bbase + TILE_B + off);
            }
            #pragma unroll
            for (int mt = 0; mt < 2; mt++)
                #pragma unroll
                for (int nt = 0; nt < 8; nt++) {
                    const int bi = (nt >> 1) * 4 + (nt & 1) * 2;
                    mma16816(acc[mt][nt], ah[mt], bh[bi], bh[bi + 1]);
                    if (PROD == 3 && full) {
                        mma16816(acc[mt][nt], ah[mt], bl[bi], bl[bi + 1]);
                        mma16816(acc[mt][nt], al[mt], bh[bi], bh[bi + 1]);
                    }
                }
        }

        CP_WAIT(1);
        __syncthreads();
    }

    // ------------------------- epilogue -------------------------
    const int mrow = m0 + wm * 32 + (lane >> 2);
    const int ncol = wn * 64 + (lane & 3) * 2;

    if (EPI == 0) {
        const int g = n0 >> 8;
        #pragma unroll
        for (int mt = 0; mt < 2; mt++) {
            #pragma unroll
            for (int nt = 0; nt < 8; nt++) {
                const int m  = mrow + mt * 16;
                const int ch = ((n0 + ncol) & 255) + nt * 8;
                float v0 = acc[mt][nt][0] + bias[(ch + 0) * 4 + g];
                float v1 = acc[mt][nt][1] + bias[(ch + 1) * 4 + g];
                float v2 = acc[mt][nt][2] + bias[(ch + 0) * 4 + g];
                float v3 = acc[mt][nt][3] + bias[(ch + 1) * 4 + g];
                if (g < 3) {
                    __half* dst = (g == 0) ? g_q : (g == 1) ? g_k : g_v;
                    *(__half2*)&dst[(size_t)m * 256 + ch]       = __floats2half2_rn(v0, v1);
                    *(__half2*)&dst[(size_t)(m + 8) * 256 + ch] = __floats2half2_rn(v2, v3);
                } else {
                    *(__nv_bfloat162*)&g_chh[(size_t)m * 256 + ch] =
                        __nv_bfloat162(__float2bfloat16(v0), __float2bfloat16(v1));
                    *(__nv_bfloat162*)&g_chh[(size_t)(m + 8) * 256 + ch] =
                        __nv_bfloat162(__float2bfloat16(v2), __float2bfloat16(v3));
                }
            }
        }
    } else if (EPI == 1) {
        #pragma unroll
        for (int mt = 0; mt < 2; mt++)
            #pragma unroll
            for (int nt = 0; nt < 8; nt++) {
                const int m = mrow + mt * 16;
                const int n = ncol + nt * 8;          // N = 128, n0 = 0
                float v0 = fmaxf(acc[mt][nt][0] + bias[n],     0.f);
                float v1 = fmaxf(acc[mt][nt][1] + bias[n + 1], 0.f);
                float v2 = fmaxf(acc[mt][nt][2] + bias[n],     0.f);
                float v3 = fmaxf(acc[mt][nt][3] + bias[n + 1], 0.f);
                *(__nv_bfloat162*)&g_th[(size_t)m * 128 + n] =
                    __nv_bfloat162(__float2bfloat16(v0), __float2bfloat16(v1));
                *(__nv_bfloat162*)&g_th[(size_t)(m + 8) * 128 + n] =
                    __nv_bfloat162(__float2bfloat16(v2), __float2bfloat16(v3));
            }
    } else if (EPI == 2) {
        #pragma unroll
        for (int mt = 0; mt < 2; mt++)
            #pragma unroll
            for (int nt = 0; nt < 8; nt++) {
                const int m = mrow + mt * 16;
                const int n = n0 + ncol + nt * 8;
                float v0 = 1.f / (1.f + expf(-(acc[mt][nt][0] + bias[n])));
                float v1 = 1.f / (1.f + expf(-(acc[mt][nt][1] + bias[n + 1])));
                float v2 = 1.f / (1.f + expf(-(acc[mt][nt][2] + bias[n])));
                float v3 = 1.f / (1.f + expf(-(acc[mt][nt][3] + bias[n + 1])));
                *(float2*)&g_gate[(size_t)m * 256 + n]       = make_float2(v0, v1);
                *(float2*)&g_gate[(size_t)(m + 8) * 256 + n] = make_float2(v2, v3);
            }
    } else { // EPI == 3: bias + smem transpose + coalesced NCHW store
        float* smT = (float*)sm;                  // [128 n][stride 132 m]
        const int ml = mrow - m0;
        #pragma unroll
        for (int mt = 0; mt < 2; mt++)
            #pragma unroll
            for (int nt = 0; nt < 8; nt++) {
                const int n = ncol + nt * 8;      // local n (0..127)
                smT[(n)     * 132 + ml + mt * 16]     = acc[mt][nt][0] + bias[n0 + n];
                smT[(n + 1) * 132 + ml + mt * 16]     = acc[mt][nt][1] + bias[n0 + n + 1];
                smT[(n)     * 132 + ml + mt * 16 + 8] = acc[mt][nt][2] + bias[n0 + n];
                smT[(n + 1) * 132 + ml + mt * 16 + 8] = acc[mt][nt][3] + bias[n0 + n + 1];
            }
        __syncthreads();
        const int nl = t >> 1, half = t & 1;
        const int bi = m0 >> 12, hw0 = m0 & 4095;
        float* orow = outp + ((size_t)(bi * 256 + n0 + nl)) * 4096 + hw0 + half * 64;
        #pragma unroll
        for (int i = 0; i < 16; i++)
            *(float4*)&orow[i * 4] = *(float4*)&smT[nl * 132 + half * 64 + i * 4];
    }
}

// ---------------------------------------------------------------------------
// Kernel: 3x3 local-window attention + gate; q/k/v fp16, writes bf16 hi/lo
// ---------------------------------------------------------------------------
__global__ void __launch_bounds__(256) attn_kernel()
{
    const int pos  = blockIdx.x;
    const int head = threadIdx.x >> 5;
    const int lane = threadIdx.x & 31;
    const int hw = pos & 4095;
    const int iy = hw >> 6, ix = hw & 63;
    const int ch = head * HD_ + lane;
    const size_t base = (size_t)pos * C_ + ch;

    const float q = __half2float(g_q[base]);
    float logit[9], vv[9];
    #pragma unroll
    for (int j = 0; j < 9; j++) {
        int dy = j / 3 - 1, dx = j % 3 - 1;
        int ny = iy + dy, nx = ix + dx;
        float p = 0.f, val = 0.f;
        if (ny >= 0 && ny < H_ && nx >= 0 && nx < W_) {
            int npos = pos + dy * 64 + dx;
            size_t nb = (size_t)npos * C_ + ch;
            p   = q * __half2float(g_k[nb]);
            val = __half2float(g_v[nb]);
        }
        #pragma unroll
        for (int off = 16; off; off >>= 1)
            p += __shfl_xor_sync(0xffffffffu, p, off);
        logit[j] = p * 0.17677669529663687f;
        vv[j] = val;
    }

    float mx = logit[0];
    #pragma unroll
    for (int j = 1; j < 9; j++) mx = fmaxf(mx, logit[j]);
    float e[9], ssum = 0.f;
    #pragma unroll
    for (int j = 0; j < 9; j++) { e[j] = __expf(logit[j] - mx); ssum += e[j]; }
    const float inv = 1.f / ssum;
    float o = 0.f;
    #pragma unroll
    for (int j = 0; j < 9; j++) o += e[j] * inv * vv[j];

    const float r = o * (1.f + g_gate[base]);
    __nv_bfloat16 hi, lo;
    split_bf16(r, hi, lo);
    g_ath[base] = hi;
    g_atl[base] = lo;
}

// ---------------------------------------------------------------------------
extern "C" void kernel_launch(void* const* d_in, const int* in_sizes, int n_in,
                              void* d_out, int out_size)
{
    const float* x     = (const float*)d_in[0];
    const float* W_qkv = (const float*)d_in[1];
    const float* b_qkv = (const float*)d_in[2];
    const float* W1    = (const float*)d_in[3];
    const float* b1    = (const float*)d_in[4];
    const float* W2    = (const float*)d_in[5];
    const float* b2    = (const float*)d_in[6];
    const float* Wp    = (const float*)d_in[7];
    const float* bp    = (const float*)d_in[8];
    float* out = (float*)d_out;

    const int SMEM3 = 3 * 4 * TILE_B;   // 96 KB (PROD=3)
    const int SMEM1 = 3 * 2 * TILE_B;   // 48 KB (PROD=1)

    cudaFuncSetAttribute(mma_gemm<0, 0,  8, 256, 3>, cudaFuncAttributeMaxDynamicSharedMemorySize, SMEM3);
    cudaFuncSetAttribute(mma_gemm<1, 2, 10, 256, 1>, cudaFuncAttributeMaxDynamicSharedMemorySize, SMEM1);
    cudaFuncSetAttribute(mma_gemm<2, 4, 12, 128, 1>, cudaFuncAttributeMaxDynamicSharedMemorySize, SMEM1);
    cudaFuncSetAttribute(mma_gemm<3, 6, 14, 256, 3>, cudaFuncAttributeMaxDynamicSharedMemorySize, SMEM3);

    // 1) weight conversion + avg pool
    convert_weights<<<1536, 256>>>(W_qkv, W1, W2, Wp);
    avgpool_kernel<<<dim3(H_, C_ / 32, B_), 256>>>(x);

    // 2) QKV GEMM: [32768,1024] = y @ Wqkv^T  -> q/k/v fp16, ch bf16
    //    (ch blocks n0>=768 run single-product)
    mma_gemm<0, 0, 8, 256, 3><<<dim3(8, 256), 256, SMEM3>>>(b_qkv, nullptr);

    // 3) gate hidden: relu(ch @ W1^T + b1) -> t bf16  (N=128, single product)
    mma_gemm<1, 2, 10, 256, 1><<<dim3(1, 256), 256, SMEM1>>>(b1, nullptr);

    // 4) gate: sigmoid(t @ W2^T + b2) -> g_gate  (N=256, K=128, single product)
    mma_gemm<2, 4, 12, 128, 1><<<dim3(2, 256), 256, SMEM1>>>(b2, nullptr);

    // 5) local attention + (1+g) -> ath/atl bf16
    attn_kernel<<<M_, 256>>>();

    // 6) projection + bias + NCHW store -> d_out
    mma_gemm<3, 6, 14, 256, 3><<<dim3(2, 256), 256, SMEM3>>>(bp, out);
}